// round 10
// baseline (speedup 1.0000x reference)
#include <cuda_runtime.h>
#include <cuda_bf16.h>

// durations [B=32, T=512] fp32, max_len=4096.
// repeats = (int)(d + 0.5); ends = inclusive cumsum; starts = ends - repeats
// out[b, t, j] = (starts[b,j] <= t < ends[b,j]) ? 1 : 0   -> [32, 4096, 512] fp32 (256 MiB)
//
// ONE fused kernel, write-only streaming. grid=2048 (best measured),
// evict-first 256-bit stores (st.global.cs.v8.f32, sm_100+): each thread
// owns 8 tokens, one 32B store per row iteration.

#define B_BATCH 32
#define T_TEXT  512
#define MAX_LEN 4096

#define BLOCKS_PER_BATCH 64
#define ROWS_PER_BLOCK   (MAX_LEN / BLOCKS_PER_BATCH)     // 64
#define FILL_THREADS     512
#define NWARPS           (FILL_THREADS / 32)              // 16
#define OCTS_PER_ROW     (T_TEXT / 8)                     // 64
#define ROWS_PER_ITER    (FILL_THREADS / OCTS_PER_ROW)    // 8
#define ITERS            (ROWS_PER_BLOCK / ROWS_PER_ITER) // 8

__global__ __launch_bounds__(FILL_THREADS, 4)
void lr_fused_kernel(const float* __restrict__ durations,
                     float* __restrict__ out)
{
    const int b    = blockIdx.y;
    const int j    = threadIdx.x;
    const int lane = j & 31;
    const int wrp  = j >> 5;

    // s[0] = 0, s[1+j] = inclusive_cumsum(rep)[j]
    __shared__ int s[T_TEXT + 1];
    __shared__ int wsum[NWARPS];

    // --- scan prologue (redundant per block; inputs L2-resident) ---
    const float d = durations[b * T_TEXT + j];
    const int rep = (int)(d + 0.5f);   // d > 0: truncation == reference cast

    int v = rep;
    #pragma unroll
    for (int off = 1; off < 32; off <<= 1) {
        int n = __shfl_up_sync(0xFFFFFFFFu, v, off);
        if (lane >= off) v += n;
    }
    if (lane == 31) wsum[wrp] = v;
    __syncthreads();

    if (wrp == 0) {
        int wv = (lane < NWARPS) ? wsum[lane] : 0;
        #pragma unroll
        for (int off = 1; off < NWARPS; off <<= 1) {
            int n = __shfl_up_sync(0xFFFFFFFFu, wv, off);
            if (lane >= off) wv += n;
        }
        if (lane < NWARPS) wsum[lane] = wv;
        if (lane == 0) s[0] = 0;
    }
    __syncthreads();

    const int warp_off = (wrp > 0) ? wsum[wrp - 1] : 0;
    s[1 + j] = v + warp_off;
    __syncthreads();

    // --- fill mainloop: each thread owns a fixed octet of 8 tokens ---
    const int q  = j & (OCTS_PER_ROW - 1);   // octet index within row
    const int tr = j >> 6;                   // 0..7 row offset within iter
    const int j0 = q * 8;

    int a[9];
    #pragma unroll
    for (int k = 0; k < 9; ++k) a[k] = s[j0 + k];

    const int t_base = blockIdx.x * ROWS_PER_BLOCK + tr;

    float* row_base = out + ((size_t)b * MAX_LEN) * T_TEXT + j0;

    #pragma unroll
    for (int it = 0; it < ITERS; ++it) {
        const int t = t_base + it * ROWS_PER_ITER;
        float v0 = (a[0] <= t && t < a[1]) ? 1.0f : 0.0f;
        float v1 = (a[1] <= t && t < a[2]) ? 1.0f : 0.0f;
        float v2 = (a[2] <= t && t < a[3]) ? 1.0f : 0.0f;
        float v3 = (a[3] <= t && t < a[4]) ? 1.0f : 0.0f;
        float v4 = (a[4] <= t && t < a[5]) ? 1.0f : 0.0f;
        float v5 = (a[5] <= t && t < a[6]) ? 1.0f : 0.0f;
        float v6 = (a[6] <= t && t < a[7]) ? 1.0f : 0.0f;
        float v7 = (a[7] <= t && t < a[8]) ? 1.0f : 0.0f;
        float* p = row_base + (size_t)t * T_TEXT;
        // 256-bit evict-first streaming store (sm_100+)
        asm volatile(
            "st.global.cs.v8.f32 [%0], {%1, %2, %3, %4, %5, %6, %7, %8};"
            :: "l"(p), "f"(v0), "f"(v1), "f"(v2), "f"(v3),
               "f"(v4), "f"(v5), "f"(v6), "f"(v7)
            : "memory");
    }
}

extern "C" void kernel_launch(void* const* d_in, const int* in_sizes, int n_in,
                              void* d_out, int out_size)
{
    const float* durations = (const float*)d_in[0];
    float* out = (float*)d_out;

    dim3 grid(BLOCKS_PER_BATCH, B_BATCH);
    lr_fused_kernel<<<grid, FILL_THREADS>>>(durations, out);
}